// round 1
// baseline (speedup 1.0000x reference)
#include <cuda_runtime.h>
#include <cuda_bf16.h>
#include <cstdint>

#define DH      128
#define NNODES  100000
#define NGRAPHS 512

// ---------------- scratch (no allocations allowed) ----------------
__device__ float g_agg[(size_t)NNODES * DH];
__device__ float g_mid[(size_t)NNODES * DH];
__device__ float g_h1 [(size_t)NNODES * DH];
__device__ float g_h2 [(size_t)NNODES * DH];
__device__ float g_h3 [(size_t)NNODES * DH];
__device__ float g_pool[NGRAPHS * 3 * DH];

// 16B vector reduction to global memory (sm_90+)
__device__ __forceinline__ void red_add_v4(float* p, float4 v) {
    asm volatile("red.global.add.v4.f32 [%0], {%1,%2,%3,%4};"
                 :: "l"(p), "f"(v.x), "f"(v.y), "f"(v.z), "f"(v.w)
                 : "memory");
}

// ---------------- zero fill ----------------
__global__ void zero_kernel(float* __restrict__ p, int n4) {
    int i = blockIdx.x * blockDim.x + threadIdx.x;
    if (i < n4) reinterpret_cast<float4*>(p)[i] = make_float4(0.f, 0.f, 0.f, 0.f);
}

// ---------------- edge scatter: agg[dst] += x[src] ----------------
// one warp per edge; lane handles one float4 of the 128-float row
__global__ void scatter_kernel(const float* __restrict__ x,
                               const int* __restrict__ src,
                               const int* __restrict__ dst,
                               float* __restrict__ agg, int E) {
    int w = (blockIdx.x * blockDim.x + threadIdx.x) >> 5;
    if (w >= E) return;
    int lane = threadIdx.x & 31;
    int s = __ldg(src + w);
    int d = __ldg(dst + w);
    float4 v = *reinterpret_cast<const float4*>(x + (size_t)s * DH + lane * 4);
    red_add_v4(agg + (size_t)d * DH + lane * 4, v);
}

// ---------------- SGEMM  out = epilogue(A(+A2) @ W) ----------------
// M x 128 x 128, 128x128 block tile, BK=16, 8x8 microtile, 256 threads
#define BM 128
#define BN 128
#define BK 16
#define TM 8
#define TN 8

template<bool ADD_AGG, bool DO_BN, bool DO_POOL>
__global__ __launch_bounds__(256, 2)
void gemm_kernel(const float* __restrict__ A, const float* __restrict__ A2,
                 const float* __restrict__ W,
                 const float* __restrict__ bias,
                 const float* __restrict__ gamma, const float* __restrict__ beta,
                 float* __restrict__ out,
                 const int* __restrict__ batch, int poolOff, int M) {
    __shared__ __align__(16) float As[BK * BM];   // transposed: As[k][m]
    __shared__ __align__(16) float Bs[BK * BN];   // Bs[k][n]

    const int tid     = threadIdx.x;
    const int rowBase = blockIdx.x * BM;
    const int tx      = tid & 15;      // 16 col groups
    const int ty      = tid >> 4;      // 16 row groups
    const int aRow    = tid >> 2;      // 0..63
    const int aCol    = (tid & 3) << 2;
    const int bRow    = tid >> 5;      // 0..7
    const int bCol    = (tid & 31) << 2;

    float acc[TM][TN] = {};

    for (int k0 = 0; k0 < DH; k0 += BK) {
        // A tile (fused x+agg for GEMM1), stored transposed
        #pragma unroll
        for (int r = 0; r < 2; ++r) {
            int row = rowBase + aRow + r * 64;
            float4 v = make_float4(0.f, 0.f, 0.f, 0.f);
            if (row < M) {
                v = *reinterpret_cast<const float4*>(A + (size_t)row * DH + k0 + aCol);
                if (ADD_AGG) {
                    float4 u = *reinterpret_cast<const float4*>(A2 + (size_t)row * DH + k0 + aCol);
                    v.x += u.x; v.y += u.y; v.z += u.z; v.w += u.w;
                }
            }
            int m = aRow + r * 64;
            As[(aCol + 0) * BM + m] = v.x;
            As[(aCol + 1) * BM + m] = v.y;
            As[(aCol + 2) * BM + m] = v.z;
            As[(aCol + 3) * BM + m] = v.w;
        }
        // B tile (row-major K x N)
        #pragma unroll
        for (int r = 0; r < 2; ++r) {
            int k = k0 + bRow + r * 8;
            *reinterpret_cast<float4*>(&Bs[(bRow + r * 8) * BN + bCol]) =
                *reinterpret_cast<const float4*>(W + (size_t)k * DH + bCol);
        }
        __syncthreads();

        #pragma unroll
        for (int kk = 0; kk < BK; ++kk) {
            float regM[TM], regN[TN];
            *reinterpret_cast<float4*>(&regM[0]) = *reinterpret_cast<const float4*>(&As[kk * BM + ty * TM]);
            *reinterpret_cast<float4*>(&regM[4]) = *reinterpret_cast<const float4*>(&As[kk * BM + ty * TM + 4]);
            *reinterpret_cast<float4*>(&regN[0]) = *reinterpret_cast<const float4*>(&Bs[kk * BN + tx * TN]);
            *reinterpret_cast<float4*>(&regN[4]) = *reinterpret_cast<const float4*>(&Bs[kk * BN + tx * TN + 4]);
            #pragma unroll
            for (int i = 0; i < TM; ++i)
                #pragma unroll
                for (int j = 0; j < TN; ++j)
                    acc[i][j] += regM[i] * regN[j];
        }
        __syncthreads();
    }

    // per-column epilogue params
    float cb[TN], cs[TN], cbt[TN];
    #pragma unroll
    for (int j = 0; j < TN; ++j) {
        int col = tx * TN + j;
        cb[j] = bias[col];
        if (DO_BN) {
            cs[j]  = gamma[col] * 0.9999950000374997f;  // 1/sqrt(1+1e-5)
            cbt[j] = beta[col];
        }
    }

    #pragma unroll
    for (int i = 0; i < TM; ++i) {
        int row = rowBase + ty * TM + i;
        if (row >= M) break;
        float vv[TN];
        #pragma unroll
        for (int j = 0; j < TN; ++j) {
            float v = acc[i][j] + cb[j];
            if (DO_BN) v = v * cs[j] + cbt[j];
            vv[j] = fmaxf(v, 0.f);
        }
        float4 o0 = make_float4(vv[0], vv[1], vv[2], vv[3]);
        float4 o1 = make_float4(vv[4], vv[5], vv[6], vv[7]);
        float4* op = reinterpret_cast<float4*>(out + (size_t)row * DH + tx * TN);
        op[0] = o0; op[1] = o1;
        if (DO_POOL) {
            int g = __ldg(batch + row);
            float* pp = g_pool + (size_t)g * (3 * DH) + poolOff + tx * TN;
            red_add_v4(pp,     o0);
            red_add_v4(pp + 4, o1);
        }
    }
}

// ---------------- final MLP: relu(pool @ lin1 + b) @ lin2 + b ----------------
__global__ void final_kernel(const float* __restrict__ pool,
                             const float* __restrict__ w1, const float* __restrict__ b1,
                             const float* __restrict__ w2, const float* __restrict__ b2,
                             float* __restrict__ out) {
    int g = blockIdx.x;        // 512 graphs
    int tid = threadIdx.x;     // 384 threads
    __shared__ float p[384];
    __shared__ float h[384];
    p[tid] = pool[(size_t)g * 384 + tid];
    __syncthreads();
    float acc = b1[tid];
    #pragma unroll 4
    for (int k = 0; k < 384; ++k) acc += p[k] * w1[(size_t)k * 384 + tid];
    h[tid] = fmaxf(acc, 0.f);
    __syncthreads();
    if (tid < 320) {                      // 10 outputs x 32 lanes
        int j = tid >> 5, lane = tid & 31;
        float s = 0.f;
        for (int k = lane; k < 384; k += 32) s += h[k] * w2[(size_t)k * 10 + j];
        #pragma unroll
        for (int o = 16; o > 0; o >>= 1) s += __shfl_down_sync(0xffffffffu, s, o);
        if (lane == 0) out[g * 10 + j] = s + b2[j];
    }
}

// ---------------- launch ----------------
extern "C" void kernel_launch(void* const* d_in, const int* in_sizes, int n_in,
                              void* d_out, int out_size) {
    const float* x     = (const float*)d_in[0];
    const int*   ei    = (const int*)d_in[1];
    const int*   batch = (const int*)d_in[2];
    const int E   = in_sizes[1] / 2;
    const int M   = in_sizes[0] / DH;
    const int* src = ei;
    const int* dst = ei + E;

    float *agg, *mid, *h1, *h2, *h3, *pool;
    cudaGetSymbolAddress((void**)&agg,  g_agg);
    cudaGetSymbolAddress((void**)&mid,  g_mid);
    cudaGetSymbolAddress((void**)&h1,   g_h1);
    cudaGetSymbolAddress((void**)&h2,   g_h2);
    cudaGetSymbolAddress((void**)&h3,   g_h3);
    cudaGetSymbolAddress((void**)&pool, g_pool);

    // zero pool accumulator
    {
        int n4 = NGRAPHS * 3 * DH / 4;
        zero_kernel<<<(n4 + 255) / 256, 256>>>(pool, n4);
    }

    const float* xin = x;
    float* houts[3] = {h1, h2, h3};
    const int gblocks = (M + BM - 1) / BM;
    const int n4agg = M * DH / 4;

    for (int l = 0; l < 3; ++l) {
        const float* w1    = (const float*)d_in[3 + 6 * l + 0];
        const float* b1    = (const float*)d_in[3 + 6 * l + 1];
        const float* gamma = (const float*)d_in[3 + 6 * l + 2];
        const float* beta  = (const float*)d_in[3 + 6 * l + 3];
        const float* w2    = (const float*)d_in[3 + 6 * l + 4];
        const float* b2    = (const float*)d_in[3 + 6 * l + 5];

        zero_kernel<<<(n4agg + 255) / 256, 256>>>(agg, n4agg);
        scatter_kernel<<<(E + 7) / 8, 256>>>(xin, src, dst, agg, E);
        gemm_kernel<true, true, false><<<gblocks, 256>>>(
            xin, agg, w1, b1, gamma, beta, mid, nullptr, 0, M);
        gemm_kernel<false, false, true><<<gblocks, 256>>>(
            mid, nullptr, w2, b2, nullptr, nullptr, houts[l], batch, l * DH, M);
        xin = houts[l];
    }

    final_kernel<<<NGRAPHS, 384>>>(pool,
                                   (const float*)d_in[21], (const float*)d_in[22],
                                   (const float*)d_in[23], (const float*)d_in[24],
                                   (float*)d_out);
}

// round 2
// speedup vs baseline: 1.4655x; 1.4655x over previous
#include <cuda_runtime.h>
#include <cuda_bf16.h>
#include <cstdint>

#define DH      128
#define NNODES  100000
#define NEDGES  1600000
#define NGRAPHS 512
#define NB_SCAN ((NNODES + 1023) / 1024)

// ---------------- scratch (no allocations allowed) ----------------
__device__ float g_agg[(size_t)NNODES * DH];
__device__ float g_mid[(size_t)NNODES * DH];
__device__ float g_h1 [(size_t)NNODES * DH];
__device__ float g_h2 [(size_t)NNODES * DH];
__device__ float g_h3 [(size_t)NNODES * DH];
__device__ float g_pool[NGRAPHS * 3 * DH];
__device__ int   g_cnt[NNODES];
__device__ int   g_rowptr[NNODES + 1];
__device__ int   g_cursor[NNODES];
__device__ int   g_col[NEDGES];
__device__ int   g_bsum[NB_SCAN];

// 16B vector reduction to global memory (sm_90+)
__device__ __forceinline__ void red_add_v4(float* p, float4 v) {
    asm volatile("red.global.add.v4.f32 [%0], {%1,%2,%3,%4};"
                 :: "l"(p), "f"(v.x), "f"(v.y), "f"(v.z), "f"(v.w)
                 : "memory");
}

// ---------------- zero fill ----------------
__global__ void zero_f4(float* __restrict__ p, int n4) {
    int i = blockIdx.x * blockDim.x + threadIdx.x;
    if (i < n4) reinterpret_cast<float4*>(p)[i] = make_float4(0.f, 0.f, 0.f, 0.f);
}
__global__ void zero_i(int* __restrict__ p, int n) {
    int i = blockIdx.x * blockDim.x + threadIdx.x;
    if (i < n) p[i] = 0;
}

// ---------------- CSR build ----------------
__global__ void hist_kernel(const int* __restrict__ dst, int* __restrict__ cnt, int E) {
    int i = blockIdx.x * blockDim.x + threadIdx.x;
    if (i < E) atomicAdd(cnt + __ldg(dst + i), 1);
}

// per-block inclusive scan -> exclusive, 1024 elems/block
__global__ void scan1_kernel(const int* __restrict__ cnt, int* __restrict__ rowptr,
                             int* __restrict__ bsum, int N) {
    __shared__ int sh[1024];
    int t = threadIdx.x;
    int i = blockIdx.x * 1024 + t;
    int v = (i < N) ? cnt[i] : 0;
    sh[t] = v;
    __syncthreads();
    #pragma unroll
    for (int off = 1; off < 1024; off <<= 1) {
        int u = (t >= off) ? sh[t - off] : 0;
        __syncthreads();
        sh[t] += u;
        __syncthreads();
    }
    if (i < N) rowptr[i] = sh[t] - v;     // exclusive within block
    if (t == 1023) bsum[blockIdx.x] = sh[t];
}

__global__ void scan2_kernel(int* __restrict__ bsum, int nb) {
    if (threadIdx.x == 0 && blockIdx.x == 0) {
        int run = 0;
        for (int i = 0; i < nb; ++i) { int c = bsum[i]; bsum[i] = run; run += c; }
    }
}

__global__ void scan3_kernel(int* __restrict__ rowptr, int* __restrict__ cursor,
                             const int* __restrict__ bsum, int N, int E) {
    int i = blockIdx.x * blockDim.x + threadIdx.x;
    if (i < N) {
        int v = rowptr[i] + bsum[i >> 10];
        rowptr[i] = v;
        cursor[i] = v;
    }
    if (i == 0) rowptr[N] = E;
}

__global__ void fill_kernel(const int* __restrict__ src, const int* __restrict__ dst,
                            int* __restrict__ cursor, int* __restrict__ col, int E) {
    int i = blockIdx.x * blockDim.x + threadIdx.x;
    if (i < E) {
        int p = atomicAdd(cursor + __ldg(dst + i), 1);
        col[p] = __ldg(src + i);
    }
}

// ---------------- gather: agg[i] = x[i] + sum_{j in N(i)} x[j] ----------------
// one warp per node; lane owns one float4 of the row
__global__ void gather_kernel(const float* __restrict__ x,
                              const int* __restrict__ rowptr,
                              const int* __restrict__ col,
                              float* __restrict__ agg, int N) {
    int w = (blockIdx.x * blockDim.x + threadIdx.x) >> 5;
    if (w >= N) return;
    int lane = threadIdx.x & 31;
    const float4* xb = reinterpret_cast<const float4*>(x);
    float4 acc = xb[(size_t)w * 32 + lane];          // fused x + agg
    int e   = __ldg(rowptr + w);
    int end = __ldg(rowptr + w + 1);
    for (; e + 4 <= end; e += 4) {
        int s0 = __ldg(col + e + 0);
        int s1 = __ldg(col + e + 1);
        int s2 = __ldg(col + e + 2);
        int s3 = __ldg(col + e + 3);
        float4 v0 = xb[(size_t)s0 * 32 + lane];
        float4 v1 = xb[(size_t)s1 * 32 + lane];
        float4 v2 = xb[(size_t)s2 * 32 + lane];
        float4 v3 = xb[(size_t)s3 * 32 + lane];
        acc.x += (v0.x + v1.x) + (v2.x + v3.x);
        acc.y += (v0.y + v1.y) + (v2.y + v3.y);
        acc.z += (v0.z + v1.z) + (v2.z + v3.z);
        acc.w += (v0.w + v1.w) + (v2.w + v3.w);
    }
    for (; e < end; ++e) {
        int s = __ldg(col + e);
        float4 v = xb[(size_t)s * 32 + lane];
        acc.x += v.x; acc.y += v.y; acc.z += v.z; acc.w += v.w;
    }
    reinterpret_cast<float4*>(agg)[(size_t)w * 32 + lane] = acc;
}

// ---------------- SGEMM  out = epilogue(A @ W) ----------------
#define BM 128
#define BN 128
#define BK 16
#define TM 8
#define TN 8

template<bool DO_BN, bool DO_POOL>
__global__ __launch_bounds__(256, 2)
void gemm_kernel(const float* __restrict__ A,
                 const float* __restrict__ W,
                 const float* __restrict__ bias,
                 const float* __restrict__ gamma, const float* __restrict__ beta,
                 float* __restrict__ out,
                 const int* __restrict__ batch, int poolOff, int M) {
    __shared__ __align__(16) float As[BK * BM];   // transposed: As[k][m]
    __shared__ __align__(16) float Bs[BK * BN];   // Bs[k][n]

    const int tid     = threadIdx.x;
    const int rowBase = blockIdx.x * BM;
    const int tx      = tid & 15;
    const int ty      = tid >> 4;
    const int aRow    = tid >> 2;
    const int aCol    = (tid & 3) << 2;
    const int bRow    = tid >> 5;
    const int bCol    = (tid & 31) << 2;

    float acc[TM][TN] = {};

    for (int k0 = 0; k0 < DH; k0 += BK) {
        #pragma unroll
        for (int r = 0; r < 2; ++r) {
            int row = rowBase + aRow + r * 64;
            float4 v = make_float4(0.f, 0.f, 0.f, 0.f);
            if (row < M)
                v = *reinterpret_cast<const float4*>(A + (size_t)row * DH + k0 + aCol);
            int m = aRow + r * 64;
            As[(aCol + 0) * BM + m] = v.x;
            As[(aCol + 1) * BM + m] = v.y;
            As[(aCol + 2) * BM + m] = v.z;
            As[(aCol + 3) * BM + m] = v.w;
        }
        #pragma unroll
        for (int r = 0; r < 2; ++r) {
            int k = k0 + bRow + r * 8;
            *reinterpret_cast<float4*>(&Bs[(bRow + r * 8) * BN + bCol]) =
                *reinterpret_cast<const float4*>(W + (size_t)k * DH + bCol);
        }
        __syncthreads();

        #pragma unroll
        for (int kk = 0; kk < BK; ++kk) {
            float regM[TM], regN[TN];
            *reinterpret_cast<float4*>(&regM[0]) = *reinterpret_cast<const float4*>(&As[kk * BM + ty * TM]);
            *reinterpret_cast<float4*>(&regM[4]) = *reinterpret_cast<const float4*>(&As[kk * BM + ty * TM + 4]);
            *reinterpret_cast<float4*>(&regN[0]) = *reinterpret_cast<const float4*>(&Bs[kk * BN + tx * TN]);
            *reinterpret_cast<float4*>(&regN[4]) = *reinterpret_cast<const float4*>(&Bs[kk * BN + tx * TN + 4]);
            #pragma unroll
            for (int i = 0; i < TM; ++i)
                #pragma unroll
                for (int j = 0; j < TN; ++j)
                    acc[i][j] += regM[i] * regN[j];
        }
        __syncthreads();
    }

    float cb[TN], cs[TN], cbt[TN];
    #pragma unroll
    for (int j = 0; j < TN; ++j) {
        int col = tx * TN + j;
        cb[j] = bias[col];
        if (DO_BN) {
            cs[j]  = gamma[col] * 0.9999950000374997f;  // 1/sqrt(1+1e-5)
            cbt[j] = beta[col];
        }
    }

    #pragma unroll
    for (int i = 0; i < TM; ++i) {
        int row = rowBase + ty * TM + i;
        if (row >= M) break;
        float vv[TN];
        #pragma unroll
        for (int j = 0; j < TN; ++j) {
            float v = acc[i][j] + cb[j];
            if (DO_BN) v = v * cs[j] + cbt[j];
            vv[j] = fmaxf(v, 0.f);
        }
        float4 o0 = make_float4(vv[0], vv[1], vv[2], vv[3]);
        float4 o1 = make_float4(vv[4], vv[5], vv[6], vv[7]);
        float4* op = reinterpret_cast<float4*>(out + (size_t)row * DH + tx * TN);
        op[0] = o0; op[1] = o1;
        if (DO_POOL) {
            int g = __ldg(batch + row);
            float* pp = g_pool + (size_t)g * (3 * DH) + poolOff + tx * TN;
            red_add_v4(pp,     o0);
            red_add_v4(pp + 4, o1);
        }
    }
}

// ---------------- final MLP ----------------
__global__ void final_kernel(const float* __restrict__ pool,
                             const float* __restrict__ w1, const float* __restrict__ b1,
                             const float* __restrict__ w2, const float* __restrict__ b2,
                             float* __restrict__ out) {
    int g = blockIdx.x;
    int tid = threadIdx.x;
    __shared__ float p[384];
    __shared__ float h[384];
    p[tid] = pool[(size_t)g * 384 + tid];
    __syncthreads();
    float acc = b1[tid];
    #pragma unroll 4
    for (int k = 0; k < 384; ++k) acc += p[k] * w1[(size_t)k * 384 + tid];
    h[tid] = fmaxf(acc, 0.f);
    __syncthreads();
    if (tid < 320) {
        int j = tid >> 5, lane = tid & 31;
        float s = 0.f;
        for (int k = lane; k < 384; k += 32) s += h[k] * w2[(size_t)k * 10 + j];
        #pragma unroll
        for (int o = 16; o > 0; o >>= 1) s += __shfl_down_sync(0xffffffffu, s, o);
        if (lane == 0) out[g * 10 + j] = s + b2[j];
    }
}

// ---------------- launch ----------------
extern "C" void kernel_launch(void* const* d_in, const int* in_sizes, int n_in,
                              void* d_out, int out_size) {
    const float* x     = (const float*)d_in[0];
    const int*   ei    = (const int*)d_in[1];
    const int*   batch = (const int*)d_in[2];
    const int E   = in_sizes[1] / 2;
    const int M   = in_sizes[0] / DH;
    const int* src = ei;
    const int* dst = ei + E;

    float *agg, *mid, *h1, *h2, *h3, *pool;
    int *cnt, *rowptr, *cursor, *col, *bsum;
    cudaGetSymbolAddress((void**)&agg,    g_agg);
    cudaGetSymbolAddress((void**)&mid,    g_mid);
    cudaGetSymbolAddress((void**)&h1,     g_h1);
    cudaGetSymbolAddress((void**)&h2,     g_h2);
    cudaGetSymbolAddress((void**)&h3,     g_h3);
    cudaGetSymbolAddress((void**)&pool,   g_pool);
    cudaGetSymbolAddress((void**)&cnt,    g_cnt);
    cudaGetSymbolAddress((void**)&rowptr, g_rowptr);
    cudaGetSymbolAddress((void**)&cursor, g_cursor);
    cudaGetSymbolAddress((void**)&col,    g_col);
    cudaGetSymbolAddress((void**)&bsum,   g_bsum);

    // ---- CSR build (once per call, amortized over 3 layers) ----
    zero_i<<<(M + 255) / 256, 256>>>(cnt, M);
    hist_kernel<<<(E + 255) / 256, 256>>>(dst, cnt, E);
    scan1_kernel<<<NB_SCAN, 1024>>>(cnt, rowptr, bsum, M);
    scan2_kernel<<<1, 32>>>(bsum, NB_SCAN);
    scan3_kernel<<<(M + 255) / 256, 256>>>(rowptr, cursor, bsum, M, E);
    fill_kernel<<<(E + 255) / 256, 256>>>(src, dst, cursor, col, E);

    // ---- zero pool accumulator ----
    {
        int n4 = NGRAPHS * 3 * DH / 4;
        zero_f4<<<(n4 + 255) / 256, 256>>>(pool, n4);
    }

    const float* xin = x;
    float* houts[3] = {h1, h2, h3};
    const int gblocks = (M + BM - 1) / BM;
    const int gatherBlocks = (M * 32 + 255) / 256;

    for (int l = 0; l < 3; ++l) {
        const float* w1    = (const float*)d_in[3 + 6 * l + 0];
        const float* b1    = (const float*)d_in[3 + 6 * l + 1];
        const float* gamma = (const float*)d_in[3 + 6 * l + 2];
        const float* beta  = (const float*)d_in[3 + 6 * l + 3];
        const float* w2    = (const float*)d_in[3 + 6 * l + 4];
        const float* b2    = (const float*)d_in[3 + 6 * l + 5];

        gather_kernel<<<gatherBlocks, 256>>>(xin, rowptr, col, agg, M);
        gemm_kernel<true, false><<<gblocks, 256>>>(
            agg, w1, b1, gamma, beta, mid, nullptr, 0, M);
        gemm_kernel<false, true><<<gblocks, 256>>>(
            mid, w2, b2, nullptr, nullptr, houts[l], batch, l * DH, M);
        xin = houts[l];
    }

    final_kernel<<<NGRAPHS, 384>>>(pool,
                                   (const float*)d_in[21], (const float*)d_in[22],
                                   (const float*)d_in[23], (const float*)d_in[24],
                                   (float*)d_out);
}

// round 3
// speedup vs baseline: 1.6312x; 1.1131x over previous
#include <cuda_runtime.h>
#include <cuda_bf16.h>
#include <cstdint>

#define DH      128
#define NNODES  100000
#define NEDGES  1600000
#define NGRAPHS 512
#define NB_SCAN ((NNODES + 1023) / 1024)

typedef unsigned long long u64;

// ---------------- scratch (no allocations allowed) ----------------
__device__ float g_agg[(size_t)NNODES * DH];
__device__ float g_mid[(size_t)NNODES * DH];
__device__ float g_h1 [(size_t)NNODES * DH];
__device__ float g_h2 [(size_t)NNODES * DH];
__device__ float g_h3 [(size_t)NNODES * DH];
__device__ float g_pool[NGRAPHS * 3 * DH];
__device__ int   g_cnt[NNODES];
__device__ int   g_rowptr[NNODES + 1];
__device__ int   g_cursor[NNODES];
__device__ int   g_col[NEDGES];
__device__ int   g_bsum[NB_SCAN];

// ---------------- f32x2 packed helpers (sm_103a FFMA2 pipe) ----------------
__device__ __forceinline__ u64 pack2(float lo, float hi) {
    u64 r; asm("mov.b64 %0, {%1, %2};" : "=l"(r) : "f"(lo), "f"(hi)); return r;
}
__device__ __forceinline__ void unpack2(u64 v, float& lo, float& hi) {
    asm("mov.b64 {%0, %1}, %2;" : "=f"(lo), "=f"(hi) : "l"(v));
}
__device__ __forceinline__ u64 ffma2(u64 a, u64 b, u64 c) {
    u64 d; asm("fma.rn.f32x2 %0, %1, %2, %3;" : "=l"(d) : "l"(a), "l"(b), "l"(c)); return d;
}

// 16B vector reduction to global memory (sm_90+)
__device__ __forceinline__ void red_add_v4(float* p, float4 v) {
    asm volatile("red.global.add.v4.f32 [%0], {%1,%2,%3,%4};"
                 :: "l"(p), "f"(v.x), "f"(v.y), "f"(v.z), "f"(v.w)
                 : "memory");
}

// ---------------- zero fill ----------------
__global__ void zero_f4(float* __restrict__ p, int n4) {
    int i = blockIdx.x * blockDim.x + threadIdx.x;
    if (i < n4) reinterpret_cast<float4*>(p)[i] = make_float4(0.f, 0.f, 0.f, 0.f);
}
__global__ void zero_i(int* __restrict__ p, int n) {
    int i = blockIdx.x * blockDim.x + threadIdx.x;
    if (i < n) p[i] = 0;
}

// ---------------- CSR build ----------------
__global__ void hist_kernel(const int* __restrict__ dst, int* __restrict__ cnt, int E) {
    int i = blockIdx.x * blockDim.x + threadIdx.x;
    if (i < E) atomicAdd(cnt + __ldg(dst + i), 1);
}

__global__ void scan1_kernel(const int* __restrict__ cnt, int* __restrict__ rowptr,
                             int* __restrict__ bsum, int N) {
    __shared__ int sh[1024];
    int t = threadIdx.x;
    int i = blockIdx.x * 1024 + t;
    int v = (i < N) ? cnt[i] : 0;
    sh[t] = v;
    __syncthreads();
    #pragma unroll
    for (int off = 1; off < 1024; off <<= 1) {
        int u = (t >= off) ? sh[t - off] : 0;
        __syncthreads();
        sh[t] += u;
        __syncthreads();
    }
    if (i < N) rowptr[i] = sh[t] - v;
    if (t == 1023) bsum[blockIdx.x] = sh[t];
}

// parallel exclusive scan of the (<=128) block sums, single block of 128 threads
__global__ void scan2_kernel(int* __restrict__ bsum, int nb) {
    __shared__ int wsum[4];
    int t = threadIdx.x;
    int lane = t & 31, wid = t >> 5;
    int v0 = (t < nb) ? bsum[t] : 0;
    int v = v0;
    #pragma unroll
    for (int o = 1; o < 32; o <<= 1) {
        int u = __shfl_up_sync(0xffffffffu, v, o);
        if (lane >= o) v += u;
    }
    if (lane == 31) wsum[wid] = v;
    __syncthreads();
    if (t < 32) {
        int w = (t < 4) ? wsum[t] : 0;
        #pragma unroll
        for (int o = 1; o < 4; o <<= 1) {
            int u = __shfl_up_sync(0xffffffffu, w, o);
            if (lane >= o) w += u;
        }
        if (t < 4) wsum[t] = w;
    }
    __syncthreads();
    int base = (wid > 0) ? wsum[wid - 1] : 0;
    if (t < nb) bsum[t] = base + v - v0;   // exclusive
}

__global__ void scan3_kernel(int* __restrict__ rowptr, int* __restrict__ cursor,
                             const int* __restrict__ bsum, int N, int E) {
    int i = blockIdx.x * blockDim.x + threadIdx.x;
    if (i < N) {
        int v = rowptr[i] + bsum[i >> 10];
        rowptr[i] = v;
        cursor[i] = v;
    }
    if (i == 0) rowptr[N] = E;
}

__global__ void fill_kernel(const int* __restrict__ src, const int* __restrict__ dst,
                            int* __restrict__ cursor, int* __restrict__ col, int E) {
    int i = blockIdx.x * blockDim.x + threadIdx.x;
    if (i < E) {
        int p = atomicAdd(cursor + __ldg(dst + i), 1);
        col[p] = __ldg(src + i);
    }
}

// ---------------- gather: agg[i] = x[i] + sum_{j in N(i)} x[j] ----------------
__global__ void gather_kernel(const float* __restrict__ x,
                              const int* __restrict__ rowptr,
                              const int* __restrict__ col,
                              float* __restrict__ agg, int N) {
    int w = (blockIdx.x * blockDim.x + threadIdx.x) >> 5;
    if (w >= N) return;
    int lane = threadIdx.x & 31;
    const float4* xb = reinterpret_cast<const float4*>(x);
    float4 acc = xb[(size_t)w * 32 + lane];
    int e   = __ldg(rowptr + w);
    int end = __ldg(rowptr + w + 1);
    for (; e + 4 <= end; e += 4) {
        int s0 = __ldg(col + e + 0);
        int s1 = __ldg(col + e + 1);
        int s2 = __ldg(col + e + 2);
        int s3 = __ldg(col + e + 3);
        float4 v0 = xb[(size_t)s0 * 32 + lane];
        float4 v1 = xb[(size_t)s1 * 32 + lane];
        float4 v2 = xb[(size_t)s2 * 32 + lane];
        float4 v3 = xb[(size_t)s3 * 32 + lane];
        acc.x += (v0.x + v1.x) + (v2.x + v3.x);
        acc.y += (v0.y + v1.y) + (v2.y + v3.y);
        acc.z += (v0.z + v1.z) + (v2.z + v3.z);
        acc.w += (v0.w + v1.w) + (v2.w + v3.w);
    }
    for (; e < end; ++e) {
        int s = __ldg(col + e);
        float4 v = xb[(size_t)s * 32 + lane];
        acc.x += v.x; acc.y += v.y; acc.z += v.z; acc.w += v.w;
    }
    reinterpret_cast<float4*>(agg)[(size_t)w * 32 + lane] = acc;
}

// ---------------- FFMA2 SGEMM  out = epilogue(A @ W) ----------------
// 128x128 block tile, BK=16, 8x8 microtile packed as 4 row-pairs x 8 cols,
// double-buffered smem stages. 256 threads, 2 CTAs/SM.
#define BM 128
#define BN 128
#define BK 16
#define TM 8
#define TN 8

template<bool DO_BN, bool DO_POOL>
__global__ __launch_bounds__(256, 2)
void gemm_kernel(const float* __restrict__ A,
                 const float* __restrict__ W,
                 const float* __restrict__ bias,
                 const float* __restrict__ gamma, const float* __restrict__ beta,
                 float* __restrict__ out,
                 const int* __restrict__ batch, int poolOff, int M) {
    __shared__ __align__(16) float As[2][BK * BM];   // transposed: As[k][m]
    __shared__ __align__(16) float Bs[2][BK * BN];   // Bs[k][n]

    const int tid     = threadIdx.x;
    const int rowBase = blockIdx.x * BM;
    const int tx      = tid & 15;
    const int ty      = tid >> 4;
    const int aRow    = tid >> 2;          // 0..63
    const int aCol    = (tid & 3) << 2;
    const int bRow    = tid >> 5;          // 0..7
    const int bCol    = (tid & 31) << 2;

    u64 acc2[4][8];                        // (row 2i, row 2i+1) x col j
    #pragma unroll
    for (int i = 0; i < 4; ++i)
        #pragma unroll
        for (int j = 0; j < 8; ++j) acc2[i][j] = 0ULL;

    float4 va[2], vb[2];

    auto loadG = [&](int k0) {
        #pragma unroll
        for (int r = 0; r < 2; ++r) {
            int row = rowBase + aRow + r * 64;
            va[r] = make_float4(0.f, 0.f, 0.f, 0.f);
            if (row < M)
                va[r] = *reinterpret_cast<const float4*>(A + (size_t)row * DH + k0 + aCol);
        }
        #pragma unroll
        for (int r = 0; r < 2; ++r) {
            int k = k0 + bRow + r * 8;
            vb[r] = *reinterpret_cast<const float4*>(W + (size_t)k * DH + bCol);
        }
    };
    auto storeS = [&](int buf) {
        #pragma unroll
        for (int r = 0; r < 2; ++r) {
            int m = aRow + r * 64;
            As[buf][(aCol + 0) * BM + m] = va[r].x;
            As[buf][(aCol + 1) * BM + m] = va[r].y;
            As[buf][(aCol + 2) * BM + m] = va[r].z;
            As[buf][(aCol + 3) * BM + m] = va[r].w;
        }
        #pragma unroll
        for (int r = 0; r < 2; ++r)
            *reinterpret_cast<float4*>(&Bs[buf][(bRow + r * 8) * BN + bCol]) = vb[r];
    };

    loadG(0);
    storeS(0);
    __syncthreads();

    #pragma unroll
    for (int k0 = 0; k0 < DH / BK; ++k0) {
        int cur = k0 & 1;
        if (k0 + 1 < DH / BK) loadG((k0 + 1) * BK);

        #pragma unroll
        for (int kk = 0; kk < BK; ++kk) {
            // regM: 4 packed row-pairs, direct 16B loads from transposed As
            ulonglong2 mp0 = *reinterpret_cast<const ulonglong2*>(&As[cur][kk * BM + ty * TM]);
            ulonglong2 mp1 = *reinterpret_cast<const ulonglong2*>(&As[cur][kk * BM + ty * TM + 4]);
            u64 rm[4] = {mp0.x, mp0.y, mp1.x, mp1.y};
            // regN: 8 broadcast pairs
            float4 n0 = *reinterpret_cast<const float4*>(&Bs[cur][kk * BN + tx * TN]);
            float4 n1 = *reinterpret_cast<const float4*>(&Bs[cur][kk * BN + tx * TN + 4]);
            u64 rn[8] = {pack2(n0.x, n0.x), pack2(n0.y, n0.y),
                         pack2(n0.z, n0.z), pack2(n0.w, n0.w),
                         pack2(n1.x, n1.x), pack2(n1.y, n1.y),
                         pack2(n1.z, n1.z), pack2(n1.w, n1.w)};
            #pragma unroll
            for (int i = 0; i < 4; ++i)
                #pragma unroll
                for (int j = 0; j < 8; ++j)
                    acc2[i][j] = ffma2(rm[i], rn[j], acc2[i][j]);
        }
        if (k0 + 1 < DH / BK) {
            storeS(cur ^ 1);
            __syncthreads();
        }
    }

    // unpack accumulators
    float accf[TM][TN];
    #pragma unroll
    for (int i2 = 0; i2 < 4; ++i2)
        #pragma unroll
        for (int j = 0; j < 8; ++j)
            unpack2(acc2[i2][j], accf[2 * i2][j], accf[2 * i2 + 1][j]);

    float cb[TN], cs[TN], cbt[TN];
    #pragma unroll
    for (int j = 0; j < TN; ++j) {
        int col = tx * TN + j;
        cb[j] = bias[col];
        if (DO_BN) {
            cs[j]  = gamma[col] * 0.9999950000374997f;  // 1/sqrt(1+1e-5)
            cbt[j] = beta[col];
        }
    }

    #pragma unroll
    for (int i = 0; i < TM; ++i) {
        int row = rowBase + ty * TM + i;
        if (row >= M) break;
        float vv[TN];
        #pragma unroll
        for (int j = 0; j < TN; ++j) {
            float v = accf[i][j] + cb[j];
            if (DO_BN) v = v * cs[j] + cbt[j];
            vv[j] = fmaxf(v, 0.f);
        }
        float4 o0 = make_float4(vv[0], vv[1], vv[2], vv[3]);
        float4 o1 = make_float4(vv[4], vv[5], vv[6], vv[7]);
        float4* op = reinterpret_cast<float4*>(out + (size_t)row * DH + tx * TN);
        op[0] = o0; op[1] = o1;
        if (DO_POOL) {
            int g = __ldg(batch + row);
            float* pp = g_pool + (size_t)g * (3 * DH) + poolOff + tx * TN;
            red_add_v4(pp,     o0);
            red_add_v4(pp + 4, o1);
        }
    }
}

// ---------------- final MLP ----------------
__global__ void final_kernel(const float* __restrict__ pool,
                             const float* __restrict__ w1, const float* __restrict__ b1,
                             const float* __restrict__ w2, const float* __restrict__ b2,
                             float* __restrict__ out) {
    int g = blockIdx.x;
    int tid = threadIdx.x;
    __shared__ float p[384];
    __shared__ float h[384];
    p[tid] = pool[(size_t)g * 384 + tid];
    __syncthreads();
    float acc = b1[tid];
    #pragma unroll 4
    for (int k = 0; k < 384; ++k) acc += p[k] * w1[(size_t)k * 384 + tid];
    h[tid] = fmaxf(acc, 0.f);
    __syncthreads();
    if (tid < 320) {
        int j = tid >> 5, lane = tid & 31;
        float s = 0.f;
        for (int k = lane; k < 384; k += 32) s += h[k] * w2[(size_t)k * 10 + j];
        #pragma unroll
        for (int o = 16; o > 0; o >>= 1) s += __shfl_down_sync(0xffffffffu, s, o);
        if (lane == 0) out[g * 10 + j] = s + b2[j];
    }
}

// ---------------- launch ----------------
extern "C" void kernel_launch(void* const* d_in, const int* in_sizes, int n_in,
                              void* d_out, int out_size) {
    const float* x     = (const float*)d_in[0];
    const int*   ei    = (const int*)d_in[1];
    const int*   batch = (const int*)d_in[2];
    const int E   = in_sizes[1] / 2;
    const int M   = in_sizes[0] / DH;
    const int* src = ei;
    const int* dst = ei + E;

    float *agg, *mid, *h1, *h2, *h3, *pool;
    int *cnt, *rowptr, *cursor, *col, *bsum;
    cudaGetSymbolAddress((void**)&agg,    g_agg);
    cudaGetSymbolAddress((void**)&mid,    g_mid);
    cudaGetSymbolAddress((void**)&h1,     g_h1);
    cudaGetSymbolAddress((void**)&h2,     g_h2);
    cudaGetSymbolAddress((void**)&h3,     g_h3);
    cudaGetSymbolAddress((void**)&pool,   g_pool);
    cudaGetSymbolAddress((void**)&cnt,    g_cnt);
    cudaGetSymbolAddress((void**)&rowptr, g_rowptr);
    cudaGetSymbolAddress((void**)&cursor, g_cursor);
    cudaGetSymbolAddress((void**)&col,    g_col);
    cudaGetSymbolAddress((void**)&bsum,   g_bsum);

    // ---- CSR build (once per call, amortized over 3 layers) ----
    zero_i<<<(M + 255) / 256, 256>>>(cnt, M);
    hist_kernel<<<(E + 255) / 256, 256>>>(dst, cnt, E);
    scan1_kernel<<<NB_SCAN, 1024>>>(cnt, rowptr, bsum, M);
    scan2_kernel<<<1, 128>>>(bsum, NB_SCAN);
    scan3_kernel<<<(M + 255) / 256, 256>>>(rowptr, cursor, bsum, M, E);
    fill_kernel<<<(E + 255) / 256, 256>>>(src, dst, cursor, col, E);

    // ---- zero pool accumulator ----
    {
        int n4 = NGRAPHS * 3 * DH / 4;
        zero_f4<<<(n4 + 255) / 256, 256>>>(pool, n4);
    }

    const float* xin = x;
    float* houts[3] = {h1, h2, h3};
    const int gblocks = (M + BM - 1) / BM;
    const int gatherBlocks = (M * 32 + 255) / 256;

    for (int l = 0; l < 3; ++l) {
        const float* w1    = (const float*)d_in[3 + 6 * l + 0];
        const float* b1    = (const float*)d_in[3 + 6 * l + 1];
        const float* gamma = (const float*)d_in[3 + 6 * l + 2];
        const float* beta  = (const float*)d_in[3 + 6 * l + 3];
        const float* w2    = (const float*)d_in[3 + 6 * l + 4];
        const float* b2    = (const float*)d_in[3 + 6 * l + 5];

        gather_kernel<<<gatherBlocks, 256>>>(xin, rowptr, col, agg, M);
        gemm_kernel<true, false><<<gblocks, 256>>>(
            agg, w1, b1, gamma, beta, mid, nullptr, 0, M);
        gemm_kernel<false, true><<<gblocks, 256>>>(
            mid, w2, b2, nullptr, nullptr, houts[l], batch, l * DH, M);
        xin = houts[l];
    }

    final_kernel<<<NGRAPHS, 384>>>(pool,
                                   (const float*)d_in[21], (const float*)d_in[22],
                                   (const float*)d_in[23], (const float*)d_in[24],
                                   (float*)d_out);
}